// round 2
// baseline (speedup 1.0000x reference)
#include <cuda_runtime.h>
#include <cuda_bf16.h>
#include <cstdint>
#include <math.h>

// Problem constants
#define Bc 32
#define Tc 96
#define INc 256
#define Hc 512
#define HEADSc 4
#define Vc 32000
#define TP1 (Tc + 1)
#define CATc ((1 + HEADSc) * Hc)   // 2560
#define G4 (4 * Hc)                // 2048
#define XK1 (INc + HEADSc * Hc)    // 2304 (lstm_in)
#define K0TOT (XK1 + Hc)           // 2816

// -------------------- device scratch (static; no runtime alloc) ------------
__device__ float g_h0[Bc * Hc];
__device__ float g_c0[Bc * Hc];
__device__ float g_c1[Bc * Hc];
__device__ float g_buf[Bc * TP1 * Hc];   // top-layer hidden history
__device__ float g_U[Bc * TP1 * Hc];     // buf_j @ Wa1[:, :H].T
__device__ float g_P[Bc * TP1 * Hc];     // buf_j @ Wa1[:, H:].T
__device__ float g_part0[4 * Bc * G4];   // k-split partials, cell0
__device__ float g_part1[2 * Bc * G4];   // k-split partials, cell1
__device__ float g_cat[(size_t)Bc * Tc * CATc];          // [h1n, cvec] rows, m = t*B+b
__device__ __nv_bfloat16 g_cat_bf[(size_t)Bc * Tc * CATc];
__device__ __nv_bfloat16 g_Wo_bf[(size_t)Vc * CATc];

__device__ __forceinline__ float sigf(float x) { return 1.0f / (1.0f + __expf(-x)); }

// -------------------- init ------------------------------------------------
__global__ void k_init() {
    int idx = blockIdx.x * 256 + threadIdx.x;     // 0..16383
    int b = idx >> 9, h = idx & (Hc - 1);
    g_h0[idx] = 0.f; g_c0[idx] = 0.f; g_c1[idx] = 0.f;
    size_t s0 = ((size_t)b * TP1) * Hc + h;       // slot 0
    g_buf[s0] = 0.f; g_U[s0] = 0.f; g_P[s0] = 0.f;
}

// -------------------- conversions -----------------------------------------
__global__ void k_cvt_wo(const float* __restrict__ src) {
    size_t n4 = (size_t)Vc * CATc / 4;
    size_t stride = (size_t)gridDim.x * 256;
    for (size_t i = (size_t)blockIdx.x * 256 + threadIdx.x; i < n4; i += stride) {
        float4 v = ((const float4*)src)[i];
        __nv_bfloat162* d = (__nv_bfloat162*)g_Wo_bf;
        d[2 * i]     = __floats2bfloat162_rn(v.x, v.y);
        d[2 * i + 1] = __floats2bfloat162_rn(v.z, v.w);
    }
}

__global__ void k_cvt_cat() {
    size_t n4 = (size_t)Bc * Tc * CATc / 4;
    size_t stride = (size_t)gridDim.x * 256;
    for (size_t i = (size_t)blockIdx.x * 256 + threadIdx.x; i < n4; i += stride) {
        float4 v = ((const float4*)g_cat)[i];
        __nv_bfloat162* d = (__nv_bfloat162*)g_cat_bf;
        d[2 * i]     = __floats2bfloat162_rn(v.x, v.y);
        d[2 * i + 1] = __floats2bfloat162_rn(v.z, v.w);
    }
}

// -------------------- attention: scores + softmax + cvec -------------------
__global__ void k_attn(int t, const float* __restrict__ Wa2,
                       const float* __restrict__ ba1, const float* __restrict__ ba2) {
    int b = blockIdx.x, tid = threadIdx.x, lane = tid & 31, w = tid >> 5;
    __shared__ float uh[Hc];
    __shared__ float wa2s[HEADSc * Hc];
    __shared__ float s_sm[TP1 * 4];

    const float* Ub = &g_U[((size_t)b * TP1 + t) * Hc];
    for (int h = tid; h < Hc; h += 256) uh[h] = Ub[h] + ba1[h];
    for (int i = tid; i < HEADSc * Hc; i += 256) wa2s[i] = Wa2[i];
    __syncthreads();

    for (int j = w; j <= t; j += 8) {
        const float* Pj = &g_P[((size_t)b * TP1 + j) * Hc];
        float a0 = 0.f, a1 = 0.f, a2 = 0.f, a3 = 0.f;
        for (int h = lane; h < Hc; h += 32) {
            float hd = fmaxf(uh[h] + Pj[h], 0.f);
            a0 = fmaf(hd, wa2s[h], a0);
            a1 = fmaf(hd, wa2s[Hc + h], a1);
            a2 = fmaf(hd, wa2s[2 * Hc + h], a2);
            a3 = fmaf(hd, wa2s[3 * Hc + h], a3);
        }
        #pragma unroll
        for (int o = 16; o; o >>= 1) {
            a0 += __shfl_xor_sync(0xffffffffu, a0, o);
            a1 += __shfl_xor_sync(0xffffffffu, a1, o);
            a2 += __shfl_xor_sync(0xffffffffu, a2, o);
            a3 += __shfl_xor_sync(0xffffffffu, a3, o);
        }
        if (lane == 0) {
            s_sm[j * 4 + 0] = fmaxf(a0 + ba2[0], 0.f);
            s_sm[j * 4 + 1] = fmaxf(a1 + ba2[1], 0.f);
            s_sm[j * 4 + 2] = fmaxf(a2 + ba2[2], 0.f);
            s_sm[j * 4 + 3] = fmaxf(a3 + ba2[3], 0.f);
        }
    }
    __syncthreads();

    if (w < HEADSc) {
        int k = w;
        float m = -1e30f;
        for (int j = lane; j <= t; j += 32) m = fmaxf(m, s_sm[j * 4 + k]);
        #pragma unroll
        for (int o = 16; o; o >>= 1) m = fmaxf(m, __shfl_xor_sync(0xffffffffu, m, o));
        float s = 0.f;
        for (int j = lane; j <= t; j += 32) s += __expf(s_sm[j * 4 + k] - m);
        #pragma unroll
        for (int o = 16; o; o >>= 1) s += __shfl_xor_sync(0xffffffffu, s, o);
        float inv = 1.f / s;
        for (int j = lane; j <= t; j += 32)
            s_sm[j * 4 + k] = __expf(s_sm[j * 4 + k] - m) * inv;
    }
    __syncthreads();

    // cvec[b, k*H + h] = sum_j att[j,k] * buf[b,j,h]
    float acc[HEADSc][2] = {};
    int h0i = tid, h1i = tid + 256;
    const float* bufb = &g_buf[(size_t)b * TP1 * Hc];
    for (int j = 0; j <= t; j++) {
        float bv0 = bufb[(size_t)j * Hc + h0i];
        float bv1 = bufb[(size_t)j * Hc + h1i];
        #pragma unroll
        for (int k = 0; k < HEADSc; k++) {
            float p = s_sm[j * 4 + k];
            acc[k][0] = fmaf(p, bv0, acc[k][0]);
            acc[k][1] = fmaf(p, bv1, acc[k][1]);
        }
    }
    float* crow = &g_cat[((size_t)t * Bc + b) * CATc + Hc];
    #pragma unroll
    for (int k = 0; k < HEADSc; k++) {
        crow[k * Hc + h0i] = acc[k][0];
        crow[k * Hc + h1i] = acc[k][1];
    }
}

// -------------------- LSTM cell-0 gate GEMM (k-split partials) -------------
__global__ void k_gates0(int t, const float* __restrict__ inputs,
                         const float* __restrict__ Wih, const float* __restrict__ Whh) {
    __shared__ float Xs[32][33];
    __shared__ float Ws[32][33];
    int tid = threadIdx.x;
    int n0 = blockIdx.x * 32;
    int kc = blockIdx.y;              // 0..3
    int kbeg = kc * 704, kend = kbeg + 704;
    float acc00 = 0, acc01 = 0, acc10 = 0, acc11 = 0;
    int na = (tid & 15) * 2, ba = (tid >> 4) * 2;

    for (int kk = kbeg; kk < kend; kk += 32) {
        #pragma unroll
        for (int i = 0; i < 4; i++) {
            int lin = tid + i * 256;
            int rr = lin >> 5, kq = lin & 31;
            int k = kk + kq;
            float xv;
            if (k < INc)       xv = inputs[((size_t)rr * Tc + t) * INc + k];
            else if (k < XK1)  xv = g_cat[((size_t)t * Bc + rr) * CATc + Hc + (k - INc)];
            else               xv = g_h0[rr * Hc + (k - XK1)];
            Xs[rr][kq] = xv;
            int n = n0 + rr;
            float wv;
            if (k < XK1) wv = Wih[(size_t)n * XK1 + k];
            else         wv = Whh[(size_t)n * Hc + (k - XK1)];
            Ws[rr][kq] = wv;
        }
        __syncthreads();
        #pragma unroll
        for (int q = 0; q < 32; q++) {
            float x0 = Xs[ba][q], x1 = Xs[ba + 1][q];
            float w0 = Ws[na][q], w1 = Ws[na + 1][q];
            acc00 = fmaf(x0, w0, acc00); acc01 = fmaf(x0, w1, acc01);
            acc10 = fmaf(x1, w0, acc10); acc11 = fmaf(x1, w1, acc11);
        }
        __syncthreads();
    }
    float* dst = &g_part0[((size_t)kc * Bc) * G4];
    dst[(size_t)ba * G4 + n0 + na]           = acc00;
    dst[(size_t)ba * G4 + n0 + na + 1]       = acc01;
    dst[(size_t)(ba + 1) * G4 + n0 + na]     = acc10;
    dst[(size_t)(ba + 1) * G4 + n0 + na + 1] = acc11;
}

// -------------------- LSTM cell-1 gate GEMM (k-split partials) -------------
__global__ void k_gates1(int t, const float* __restrict__ Wih, const float* __restrict__ Whh) {
    __shared__ float Xs[32][33];
    __shared__ float Ws[32][33];
    int tid = threadIdx.x;
    int n0 = blockIdx.x * 32;
    int kc = blockIdx.y;              // 0..1
    int kbeg = kc * 512, kend = kbeg + 512;
    float acc00 = 0, acc01 = 0, acc10 = 0, acc11 = 0;
    int na = (tid & 15) * 2, ba = (tid >> 4) * 2;

    for (int kk = kbeg; kk < kend; kk += 32) {
        #pragma unroll
        for (int i = 0; i < 4; i++) {
            int lin = tid + i * 256;
            int rr = lin >> 5, kq = lin & 31;
            int k = kk + kq;
            float xv, wv;
            int n = n0 + rr;
            if (k < Hc) {
                xv = g_h0[rr * Hc + k];
                wv = Wih[(size_t)n * Hc + k];
            } else {
                xv = g_buf[((size_t)rr * TP1 + t) * Hc + (k - Hc)];
                wv = Whh[(size_t)n * Hc + (k - Hc)];
            }
            Xs[rr][kq] = xv;
            Ws[rr][kq] = wv;
        }
        __syncthreads();
        #pragma unroll
        for (int q = 0; q < 32; q++) {
            float x0 = Xs[ba][q], x1 = Xs[ba + 1][q];
            float w0 = Ws[na][q], w1 = Ws[na + 1][q];
            acc00 = fmaf(x0, w0, acc00); acc01 = fmaf(x0, w1, acc01);
            acc10 = fmaf(x1, w0, acc10); acc11 = fmaf(x1, w1, acc11);
        }
        __syncthreads();
    }
    float* dst = &g_part1[((size_t)kc * Bc) * G4];
    dst[(size_t)ba * G4 + n0 + na]           = acc00;
    dst[(size_t)ba * G4 + n0 + na + 1]       = acc01;
    dst[(size_t)(ba + 1) * G4 + n0 + na]     = acc10;
    dst[(size_t)(ba + 1) * G4 + n0 + na + 1] = acc11;
}

// -------------------- cell updates -----------------------------------------
__global__ void k_cell0(const float* __restrict__ bih, const float* __restrict__ bhh) {
    int idx = blockIdx.x * 256 + threadIdx.x;
    int b = idx >> 9, h = idx & (Hc - 1);
    float gi = 0, gf = 0, gg = 0, go = 0;
    #pragma unroll
    for (int kc = 0; kc < 4; kc++) {
        const float* p = &g_part0[((size_t)kc * Bc + b) * G4];
        gi += p[h]; gf += p[h + Hc]; gg += p[h + 2 * Hc]; go += p[h + 3 * Hc];
    }
    gi += bih[h] + bhh[h];
    gf += bih[h + Hc] + bhh[h + Hc];
    gg += bih[h + 2 * Hc] + bhh[h + 2 * Hc];
    go += bih[h + 3 * Hc] + bhh[h + 3 * Hc];
    float c = sigf(gf) * g_c0[idx] + sigf(gi) * tanhf(gg);
    g_c0[idx] = c;
    g_h0[idx] = sigf(go) * tanhf(c);
}

__global__ void k_cell1(int t, const float* __restrict__ bih, const float* __restrict__ bhh) {
    int idx = blockIdx.x * 256 + threadIdx.x;
    int b = idx >> 9, h = idx & (Hc - 1);
    float gi = 0, gf = 0, gg = 0, go = 0;
    #pragma unroll
    for (int kc = 0; kc < 2; kc++) {
        const float* p = &g_part1[((size_t)kc * Bc + b) * G4];
        gi += p[h]; gf += p[h + Hc]; gg += p[h + 2 * Hc]; go += p[h + 3 * Hc];
    }
    gi += bih[h] + bhh[h];
    gf += bih[h + Hc] + bhh[h + Hc];
    gg += bih[h + 2 * Hc] + bhh[h + 2 * Hc];
    go += bih[h + 3 * Hc] + bhh[h + 3 * Hc];
    float c = sigf(gf) * g_c1[idx] + sigf(gi) * tanhf(gg);
    g_c1[idx] = c;
    float hn = sigf(go) * tanhf(c);
    g_buf[((size_t)b * TP1 + t + 1) * Hc + h] = hn;
    g_cat[((size_t)t * Bc + b) * CATc + h]    = hn;
}

// -------------------- incremental Wa1 projection of new h1n -----------------
__global__ void k_proj(int t, const float* __restrict__ Wa1) {
    __shared__ float Xs[32][129];
    __shared__ float Ws[16][129];
    int tid = threadIdx.x;
    int o0 = blockIdx.x * 16;   // 0..1023 output index (U: 0..511, P: 512..1023)
    int g = tid & 15, bb = tid >> 4;
    float acc0 = 0.f, acc1 = 0.f;

    for (int kk = 0; kk < Hc; kk += 128) {
        #pragma unroll
        for (int i = 0; i < 16; i++) {
            int lin = tid + i * 256;
            int rr = lin >> 7, kq = lin & 127;
            Xs[rr][kq] = g_buf[((size_t)rr * TP1 + t + 1) * Hc + kk + kq];
        }
        #pragma unroll
        for (int i = 0; i < 8; i++) {
            int lin = tid + i * 256;
            int rr = lin >> 7, kq = lin & 127;
            int oo = o0 + rr;
            int row = (oo < Hc) ? oo : (oo - Hc);
            int col = (oo < Hc) ? (kk + kq) : (Hc + kk + kq);
            Ws[rr][kq] = Wa1[(size_t)row * (2 * Hc) + col];
        }
        __syncthreads();
        #pragma unroll
        for (int q = 0; q < 128; q++) {
            float wv = Ws[g][q];
            acc0 = fmaf(Xs[bb][q], wv, acc0);
            acc1 = fmaf(Xs[bb + 16][q], wv, acc1);
        }
        __syncthreads();
    }
    int oo = o0 + g;
    if (oo < Hc) {
        g_U[((size_t)bb * TP1 + t + 1) * Hc + oo]        = acc0;
        g_U[((size_t)(bb + 16) * TP1 + t + 1) * Hc + oo] = acc1;
    } else {
        g_P[((size_t)bb * TP1 + t + 1) * Hc + (oo - Hc)]        = acc0;
        g_P[((size_t)(bb + 16) * TP1 + t + 1) * Hc + (oo - Hc)] = acc1;
    }
}

// -------------------- batched logits GEMM (bf16 mma, fp32 accum) -----------
__device__ __forceinline__ void mma16816(float* d, const uint32_t* a, const uint32_t* b) {
    asm volatile(
        "mma.sync.aligned.m16n8k16.row.col.f32.bf16.bf16.f32 "
        "{%0,%1,%2,%3}, {%4,%5,%6,%7}, {%8,%9}, {%0,%1,%2,%3};\n"
        : "+f"(d[0]), "+f"(d[1]), "+f"(d[2]), "+f"(d[3])
        : "r"(a[0]), "r"(a[1]), "r"(a[2]), "r"(a[3]), "r"(b[0]), "r"(b[1]));
}

#define SST 48  // smem row stride (elements); 96B rows -> 16B aligned uint4 stores

__global__ void __launch_bounds__(256) k_logits(const float* __restrict__ bo,
                                                float* __restrict__ out) {
    __shared__ __nv_bfloat16 As[2][128 * SST];
    __shared__ __nv_bfloat16 Bs[2][128 * SST];
    int m0 = blockIdx.y * 128, n0 = blockIdx.x * 128;
    int tid = threadIdx.x, lane = tid & 31, wid = tid >> 5;
    int wm = wid >> 2, wn = wid & 3;   // 2x4 warps; warp tile 64m x 32n
    float acc[4][4][4];
    #pragma unroll
    for (int i = 0; i < 4; i++)
        #pragma unroll
        for (int j = 0; j < 4; j++)
            #pragma unroll
            for (int q = 0; q < 4; q++) acc[i][j][q] = 0.f;

    uint4 ra[2], rb[2];
    int gr = lane >> 2, cc = (lane & 3) * 2;
    int mb = wm * 64, nb = wn * 32;

    // fetch tile kt into registers
    auto fetch = [&](int ko) {
        #pragma unroll
        for (int i = 0; i < 2; i++) {
            int lin = tid + i * 256;
            int r = lin >> 2, kq = lin & 3;
            ra[i] = *(const uint4*)&g_cat_bf[(size_t)(m0 + r) * CATc + ko + kq * 8];
            rb[i] = *(const uint4*)&g_Wo_bf[(size_t)(n0 + r) * CATc + ko + kq * 8];
        }
    };
    auto stash = [&](int s) {
        #pragma unroll
        for (int i = 0; i < 2; i++) {
            int lin = tid + i * 256;
            int r = lin >> 2, kq = lin & 3;
            *(uint4*)&As[s][r * SST + kq * 8] = ra[i];
            *(uint4*)&Bs[s][r * SST + kq * 8] = rb[i];
        }
    };
    auto compute = [&](int s) {
        #pragma unroll
        for (int ks = 0; ks < 32; ks += 16) {
            uint32_t af[4][4], bfr[4][2];
            #pragma unroll
            for (int mi = 0; mi < 4; mi++) {
                const __nv_bfloat16* base = &As[s][(mb + mi * 16 + gr) * SST + ks + cc];
                af[mi][0] = *(const uint32_t*)base;
                af[mi][1] = *(const uint32_t*)(base + 8 * SST);
                af[mi][2] = *(const uint32_t*)(base + 8);
                af[mi][3] = *(const uint32_t*)(base + 8 * SST + 8);
            }
            #pragma unroll
            for (int ni = 0; ni < 4; ni++) {
                const __nv_bfloat16* bbase = &Bs[s][(nb + ni * 8 + gr) * SST + ks + cc];
                bfr[ni][0] = *(const uint32_t*)bbase;
                bfr[ni][1] = *(const uint32_t*)(bbase + 8);
            }
            #pragma unroll
            for (int mi = 0; mi < 4; mi++)
                #pragma unroll
                for (int ni = 0; ni < 4; ni++)
                    mma16816(acc[mi][ni], af[mi], bfr[ni]);
        }
    };

    fetch(0); stash(0);
    __syncthreads();
    for (int kt = 0; kt < 80; kt++) {
        if (kt < 79) fetch((kt + 1) * 32);
        compute(kt & 1);
        if (kt < 79) stash((kt + 1) & 1);
        __syncthreads();
    }

    // epilogue: + bias, remap m=t*B+b -> row b*T+t
    #pragma unroll
    for (int mi = 0; mi < 4; mi++) {
        #pragma unroll
        for (int ni = 0; ni < 4; ni++) {
            int m = m0 + mb + mi * 16 + gr;
            int n = n0 + nb + ni * 8 + cc;
            float b0 = bo[n], b1 = bo[n + 1];
            int bi = m & 31, tt = m >> 5;
            size_t r0 = ((size_t)bi * Tc + tt) * Vc;
            out[r0 + n]     = acc[mi][ni][0] + b0;
            out[r0 + n + 1] = acc[mi][ni][1] + b1;
            int m2 = m + 8;
            int bi2 = m2 & 31, tt2 = m2 >> 5;
            size_t r1 = ((size_t)bi2 * Tc + tt2) * Vc;
            out[r1 + n]     = acc[mi][ni][2] + b0;
            out[r1 + n + 1] = acc[mi][ni][3] + b1;
        }
    }
}

// -------------------- row-wise log-softmax ---------------------------------
__global__ void k_lsm(float* __restrict__ out) {
    __shared__ float red[8];
    size_t base = (size_t)blockIdx.x * Vc;
    int tid = threadIdx.x, lane = tid & 31, w = tid >> 5;
    float m = -1e30f;
    for (int i = tid; i < Vc; i += 256) m = fmaxf(m, out[base + i]);
    #pragma unroll
    for (int o = 16; o; o >>= 1) m = fmaxf(m, __shfl_xor_sync(0xffffffffu, m, o));
    if (lane == 0) red[w] = m;
    __syncthreads();
    if (tid == 0) {
        float mm = red[0];
        #pragma unroll
        for (int i = 1; i < 8; i++) mm = fmaxf(mm, red[i]);
        red[0] = mm;
    }
    __syncthreads();
    m = red[0];
    __syncthreads();
    float s = 0.f;
    for (int i = tid; i < Vc; i += 256) s += __expf(out[base + i] - m);
    #pragma unroll
    for (int o = 16; o; o >>= 1) s += __shfl_xor_sync(0xffffffffu, s, o);
    if (lane == 0) red[w] = s;
    __syncthreads();
    if (tid == 0) {
        float ss = 0.f;
        #pragma unroll
        for (int i = 1; i < 8; i++) ss += red[i];
        red[0] += ss;
    }
    __syncthreads();
    float lse = m + logf(red[0]);
    for (int i = tid; i < Vc; i += 256) out[base + i] -= lse;
}

// -------------------- launch -----------------------------------------------
extern "C" void kernel_launch(void* const* d_in, const int* in_sizes, int n_in,
                              void* d_out, int out_size) {
    const float* inputs = (const float*)d_in[0];
    const float* W_ih0  = (const float*)d_in[1];
    const float* W_hh0  = (const float*)d_in[2];
    const float* b_ih0  = (const float*)d_in[3];
    const float* b_hh0  = (const float*)d_in[4];
    const float* W_ih1  = (const float*)d_in[5];
    const float* W_hh1  = (const float*)d_in[6];
    const float* b_ih1  = (const float*)d_in[7];
    const float* b_hh1  = (const float*)d_in[8];
    const float* Wa1    = (const float*)d_in[9];
    const float* ba1    = (const float*)d_in[10];
    const float* Wa2    = (const float*)d_in[11];
    const float* ba2    = (const float*)d_in[12];
    const float* Wo     = (const float*)d_in[13];
    const float* bo     = (const float*)d_in[14];
    float* out = (float*)d_out;

    k_init<<<64, 256>>>();
    k_cvt_wo<<<40000, 256>>>(Wo);

    for (int t = 0; t < Tc; t++) {
        k_attn<<<Bc, 256>>>(t, Wa2, ba1, ba2);
        dim3 g0(64, 4);
        k_gates0<<<g0, 256>>>(t, inputs, W_ih0, W_hh0);
        k_cell0<<<64, 256>>>(b_ih0, b_hh0);
        dim3 g1(64, 2);
        k_gates1<<<g1, 256>>>(t, W_ih1, W_hh1);
        k_cell1<<<64, 256>>>(t, b_ih1, b_hh1);
        k_proj<<<64, 256>>>(t, Wa1);
    }

    k_cvt_cat<<<7680, 256>>>();
    dim3 gg(Vc / 128, (Bc * Tc) / 128);   // (250, 24)
    k_logits<<<gg, 256>>>(bo, out);
    k_lsm<<<Bc * Tc, 256>>>(out);
}

// round 4
// speedup vs baseline: 1.6758x; 1.6758x over previous
#include <cuda_runtime.h>
#include <cuda_bf16.h>
#include <cstdint>
#include <math.h>

// Problem constants
#define Bc 32
#define Tc 96
#define INc 256
#define Hc 512
#define HEADSc 4
#define Vc 32000
#define TP1 (Tc + 1)
#define CATc ((1 + HEADSc) * Hc)   // 2560
#define G4 (4 * Hc)                // 2048
#define XK0 2816                   // gates0 K: [inp 256 | cvec 2048 | h0 512]
#define XK1c 1024                  // gates1 K: [h0 | h1]

// -------------------- device scratch (static; no runtime alloc) ------------
__device__ float g_c0[Bc * Hc];
__device__ float g_c1[Bc * Hc];
__device__ float g_buf[Bc * TP1 * Hc];   // top-layer hidden history
__device__ float g_U[Bc * TP1 * Hc];     // buf_j @ Wa1[:, :H].T
__device__ float g_P[Bc * TP1 * Hc];     // buf_j @ Wa1[:, H:].T
__device__ float g_X0[Bc * XK0];         // packed gates0 input
__device__ float g_X1[Bc * XK1c];        // packed gates1 input
__device__ float g_W0r[(size_t)G4 * XK0];    // [Wih0|Whh0], tf32-rounded
__device__ float g_W1r[(size_t)G4 * XK1c];   // [Wih1|Whh1], tf32-rounded
__device__ float g_War[(size_t)1024 * Hc];   // Wa1 reorganized [U rows; P rows]
__device__ float g_part0[11 * Bc * G4];  // k-split partials, cell0
__device__ float g_part1[8 * Bc * G4];   // k-split partials, cell1
__device__ float g_cat[(size_t)Bc * Tc * CATc];          // [h1n, cvec] rows, m = t*B+b
__device__ __nv_bfloat16 g_cat_bf[(size_t)Bc * Tc * CATc];
__device__ __nv_bfloat16 g_Wo_bf[(size_t)Vc * CATc];

__device__ __forceinline__ float sigf(float x) { return 1.0f / (1.0f + __expf(-x)); }

__device__ __forceinline__ uint32_t tf32r(float x) {
    uint32_t u;
    asm("cvt.rna.tf32.f32 %0, %1;" : "=r"(u) : "f"(x));
    return u;
}

// -------------------- init ------------------------------------------------
__global__ void k_init() {
    int idx = blockIdx.x * 256 + threadIdx.x;     // 0..16383
    int b = idx >> 9, h = idx & (Hc - 1);
    g_c0[idx] = 0.f; g_c1[idx] = 0.f;
    g_X0[b * XK0 + 2304 + h] = 0.f;               // h0(t=0) = 0
    g_X1[b * XK1c + h] = 0.f;                     // h0
    g_X1[b * XK1c + Hc + h] = 0.f;                // h1(t=0) = 0
    size_t s0 = ((size_t)b * TP1) * Hc + h;       // slot 0
    g_buf[s0] = 0.f; g_U[s0] = 0.f; g_P[s0] = 0.f;
}

// -------------------- weight prep (pack + tf32 round) ----------------------
__global__ void k_prep_w0(const float* __restrict__ Wih, const float* __restrict__ Whh) {
    size_t n4 = (size_t)G4 * XK0 / 4;
    size_t stride = (size_t)gridDim.x * 256;
    for (size_t i = (size_t)blockIdx.x * 256 + threadIdx.x; i < n4; i += stride) {
        int n = (int)(i / (XK0 / 4));
        int k4 = (int)(i % (XK0 / 4)) * 4;
        float4 v;
        if (k4 < 2304) v = *(const float4*)&Wih[(size_t)n * 2304 + k4];
        else           v = *(const float4*)&Whh[(size_t)n * Hc + (k4 - 2304)];
        uint4 r = {tf32r(v.x), tf32r(v.y), tf32r(v.z), tf32r(v.w)};
        *(uint4*)&g_W0r[i * 4] = r;
    }
}

__global__ void k_prep_w1(const float* __restrict__ Wih, const float* __restrict__ Whh) {
    size_t n4 = (size_t)G4 * XK1c / 4;
    size_t stride = (size_t)gridDim.x * 256;
    for (size_t i = (size_t)blockIdx.x * 256 + threadIdx.x; i < n4; i += stride) {
        int n = (int)(i / (XK1c / 4));
        int k4 = (int)(i % (XK1c / 4)) * 4;
        float4 v;
        if (k4 < Hc) v = *(const float4*)&Wih[(size_t)n * Hc + k4];
        else         v = *(const float4*)&Whh[(size_t)n * Hc + (k4 - Hc)];
        uint4 r = {tf32r(v.x), tf32r(v.y), tf32r(v.z), tf32r(v.w)};
        *(uint4*)&g_W1r[i * 4] = r;
    }
}

__global__ void k_prep_wa(const float* __restrict__ Wa1) {
    size_t n4 = (size_t)1024 * Hc / 4;
    size_t stride = (size_t)gridDim.x * 256;
    for (size_t i = (size_t)blockIdx.x * 256 + threadIdx.x; i < n4; i += stride) {
        int o = (int)(i / (Hc / 4));
        int k4 = (int)(i % (Hc / 4)) * 4;
        float4 v;
        if (o < Hc) v = *(const float4*)&Wa1[(size_t)o * (2 * Hc) + k4];
        else        v = *(const float4*)&Wa1[(size_t)(o - Hc) * (2 * Hc) + Hc + k4];
        uint4 r = {tf32r(v.x), tf32r(v.y), tf32r(v.z), tf32r(v.w)};
        *(uint4*)&g_War[i * 4] = r;
    }
}

// -------------------- conversions -----------------------------------------
__global__ void k_cvt_wo(const float* __restrict__ src) {
    size_t n4 = (size_t)Vc * CATc / 4;
    size_t stride = (size_t)gridDim.x * 256;
    for (size_t i = (size_t)blockIdx.x * 256 + threadIdx.x; i < n4; i += stride) {
        float4 v = ((const float4*)src)[i];
        __nv_bfloat162* d = (__nv_bfloat162*)g_Wo_bf;
        d[2 * i]     = __floats2bfloat162_rn(v.x, v.y);
        d[2 * i + 1] = __floats2bfloat162_rn(v.z, v.w);
    }
}

__global__ void k_cvt_cat() {
    size_t n4 = (size_t)Bc * Tc * CATc / 4;
    size_t stride = (size_t)gridDim.x * 256;
    for (size_t i = (size_t)blockIdx.x * 256 + threadIdx.x; i < n4; i += stride) {
        float4 v = ((const float4*)g_cat)[i];
        __nv_bfloat162* d = (__nv_bfloat162*)g_cat_bf;
        d[2 * i]     = __floats2bfloat162_rn(v.x, v.y);
        d[2 * i + 1] = __floats2bfloat162_rn(v.z, v.w);
    }
}

// -------------------- attention: scores + softmax + cvec -------------------
__global__ void k_attn(int t, const float* __restrict__ inputs,
                       const float* __restrict__ Wa2,
                       const float* __restrict__ ba1, const float* __restrict__ ba2) {
    int b = blockIdx.x, tid = threadIdx.x, lane = tid & 31, w = tid >> 5;
    __shared__ float uh[Hc];
    __shared__ float wa2s[HEADSc * Hc];
    __shared__ float s_sm[TP1 * 4];

    // pack current input token into g_X0
    if (tid < 64) {
        ((float4*)&g_X0[b * XK0])[tid] =
            ((const float4*)&inputs[((size_t)b * Tc + t) * INc])[tid];
    }

    const float* Ub = &g_U[((size_t)b * TP1 + t) * Hc];
    for (int h = tid; h < Hc; h += 256) uh[h] = Ub[h] + ba1[h];
    for (int i = tid; i < HEADSc * Hc; i += 256) wa2s[i] = Wa2[i];
    __syncthreads();

    for (int j = w; j <= t; j += 8) {
        const float* Pj = &g_P[((size_t)b * TP1 + j) * Hc];
        float a0 = 0.f, a1 = 0.f, a2 = 0.f, a3 = 0.f;
        for (int h = lane; h < Hc; h += 32) {
            float hd = fmaxf(uh[h] + Pj[h], 0.f);
            a0 = fmaf(hd, wa2s[h], a0);
            a1 = fmaf(hd, wa2s[Hc + h], a1);
            a2 = fmaf(hd, wa2s[2 * Hc + h], a2);
            a3 = fmaf(hd, wa2s[3 * Hc + h], a3);
        }
        #pragma unroll
        for (int o = 16; o; o >>= 1) {
            a0 += __shfl_xor_sync(0xffffffffu, a0, o);
            a1 += __shfl_xor_sync(0xffffffffu, a1, o);
            a2 += __shfl_xor_sync(0xffffffffu, a2, o);
            a3 += __shfl_xor_sync(0xffffffffu, a3, o);
        }
        if (lane == 0) {
            s_sm[j * 4 + 0] = fmaxf(a0 + ba2[0], 0.f);
            s_sm[j * 4 + 1] = fmaxf(a1 + ba2[1], 0.f);
            s_sm[j * 4 + 2] = fmaxf(a2 + ba2[2], 0.f);
            s_sm[j * 4 + 3] = fmaxf(a3 + ba2[3], 0.f);
        }
    }
    __syncthreads();

    if (w < HEADSc) {
        int k = w;
        float m = -1e30f;
        for (int j = lane; j <= t; j += 32) m = fmaxf(m, s_sm[j * 4 + k]);
        #pragma unroll
        for (int o = 16; o; o >>= 1) m = fmaxf(m, __shfl_xor_sync(0xffffffffu, m, o));
        float s = 0.f;
        for (int j = lane; j <= t; j += 32) s += __expf(s_sm[j * 4 + k] - m);
        #pragma unroll
        for (int o = 16; o; o >>= 1) s += __shfl_xor_sync(0xffffffffu, s, o);
        float inv = 1.f / s;
        for (int j = lane; j <= t; j += 32)
            s_sm[j * 4 + k] = __expf(s_sm[j * 4 + k] - m) * inv;
    }
    __syncthreads();

    // cvec[b, k*H + h] = sum_j att[j,k] * buf[b,j,h]
    float acc[HEADSc][2] = {};
    int h0i = tid, h1i = tid + 256;
    const float* bufb = &g_buf[(size_t)b * TP1 * Hc];
    for (int j = 0; j <= t; j++) {
        float bv0 = bufb[(size_t)j * Hc + h0i];
        float bv1 = bufb[(size_t)j * Hc + h1i];
        #pragma unroll
        for (int k = 0; k < HEADSc; k++) {
            float p = s_sm[j * 4 + k];
            acc[k][0] = fmaf(p, bv0, acc[k][0]);
            acc[k][1] = fmaf(p, bv1, acc[k][1]);
        }
    }
    float* crow = &g_cat[((size_t)t * Bc + b) * CATc + Hc];
    float* xrow = &g_X0[b * XK0 + INc];
    #pragma unroll
    for (int k = 0; k < HEADSc; k++) {
        crow[k * Hc + h0i] = acc[k][0];
        crow[k * Hc + h1i] = acc[k][1];
        xrow[k * Hc + h0i] = acc[k][0];
        xrow[k * Hc + h1i] = acc[k][1];
    }
}

// -------------------- TF32 tensor-core GEMM: C[32 x N] k-split -------------
__device__ __forceinline__ void mma_tf32(float* d, const uint32_t* a, const uint32_t* b) {
    asm volatile(
        "mma.sync.aligned.m16n8k8.row.col.f32.tf32.tf32.f32 "
        "{%0,%1,%2,%3}, {%4,%5,%6,%7}, {%8,%9}, {%0,%1,%2,%3};\n"
        : "+f"(d[0]), "+f"(d[1]), "+f"(d[2]), "+f"(d[3])
        : "r"(a[0]), "r"(a[1]), "r"(a[2]), "r"(a[3]), "r"(b[0]), "r"(b[1]));
}

// swizzled smem index for [row][col] tiles (32 cols), stride 32, XOR on 4-col quads
#define SWZ(r, c) (((r) << 5) + (((((c) >> 2) ^ ((r) & 7)) << 2) | ((c) & 3)))

// WHICH: 0 = gates0, 1 = gates1, 2 = proj (writes U/P directly)
template <int WHICH>
__global__ void __launch_bounds__(128) k_gemm(int t) {
    constexpr int N      = (WHICH == 2) ? 1024 : 2048;
    constexpr int LDW    = (WHICH == 0) ? XK0 : (WHICH == 1 ? XK1c : Hc);
    constexpr int KSLICE = (WHICH == 0) ? 256 : (WHICH == 1 ? 128 : 512);
    constexpr int CHUNKS = KSLICE / 32;

    const float* X; int ldx;
    const float* W;
    float* part = nullptr;
    if (WHICH == 0) { X = g_X0; ldx = XK0; W = g_W0r; part = g_part0; }
    else if (WHICH == 1) { X = g_X1; ldx = XK1c; W = g_W1r; part = g_part1; }
    else { X = g_buf + (size_t)(t + 1) * Hc; ldx = TP1 * Hc; W = g_War; }

    __shared__ uint32_t Xs[2][32 * 32];
    __shared__ uint32_t Ws[2][128 * 32];

    const int tid = threadIdx.x, lane = tid & 31, wp = tid >> 5;
    const int n0 = blockIdx.x * 128;
    const int kbeg = blockIdx.y * KSLICE;
    const int xr = tid >> 3, q = tid & 7;

    float acc[2][4][4];
    #pragma unroll
    for (int i = 0; i < 2; i++)
        #pragma unroll
        for (int j = 0; j < 4; j++)
            #pragma unroll
            for (int p = 0; p < 4; p++) acc[i][j][p] = 0.f;

    float4 rx[2], rw[8];

    auto FETCH = [&](int ko) {
        #pragma unroll
        for (int i = 0; i < 2; i++)
            rx[i] = *(const float4*)&X[(size_t)(xr + i * 16) * ldx + ko + q * 4];
        #pragma unroll
        for (int i = 0; i < 8; i++)
            rw[i] = *(const float4*)&W[(size_t)(n0 + xr + i * 16) * LDW + ko + q * 4];
    };
    auto STASH = [&](int s) {
        #pragma unroll
        for (int i = 0; i < 2; i++) {
            int row = xr + i * 16;
            uint4 v = {tf32r(rx[i].x), tf32r(rx[i].y), tf32r(rx[i].z), tf32r(rx[i].w)};
            *(uint4*)&Xs[s][(row << 5) + (((q ^ (row & 7))) << 2)] = v;
        }
        #pragma unroll
        for (int i = 0; i < 8; i++) {
            int row = xr + i * 16;
            uint4 v = *(uint4*)&rw[i];   // pre-rounded in prep
            *(uint4*)&Ws[s][(row << 5) + (((q ^ (row & 7))) << 2)] = v;
        }
    };
    const int arow = lane >> 2, bcol = lane & 3;
    auto COMP = [&](int s) {
        #pragma unroll
        for (int k8 = 0; k8 < 4; k8++) {
            uint32_t a[2][4], bb[4][2];
            int c0 = k8 * 8 + bcol, c1 = c0 + 4;
            #pragma unroll
            for (int mt = 0; mt < 2; mt++) {
                int r0 = arow + mt * 16, r1 = r0 + 8;
                a[mt][0] = Xs[s][SWZ(r0, c0)];
                a[mt][1] = Xs[s][SWZ(r1, c0)];
                a[mt][2] = Xs[s][SWZ(r0, c1)];
                a[mt][3] = Xs[s][SWZ(r1, c1)];
            }
            #pragma unroll
            for (int ni = 0; ni < 4; ni++) {
                int n = wp * 32 + ni * 8 + arow;
                bb[ni][0] = Ws[s][SWZ(n, c0)];
                bb[ni][1] = Ws[s][SWZ(n, c1)];
            }
            #pragma unroll
            for (int mt = 0; mt < 2; mt++)
                #pragma unroll
                for (int ni = 0; ni < 4; ni++)
                    mma_tf32(acc[mt][ni], a[mt], bb[ni]);
        }
    };

    FETCH(kbeg); STASH(0);
    __syncthreads();
    #pragma unroll 1
    for (int c = 0; c < CHUNKS; c++) {
        if (c + 1 < CHUNKS) FETCH(kbeg + (c + 1) * 32);
        COMP(c & 1);
        if (c + 1 < CHUNKS) STASH((c + 1) & 1);
        __syncthreads();
    }

    int kc = blockIdx.y;
    #pragma unroll
    for (int mt = 0; mt < 2; mt++) {
        #pragma unroll
        for (int ni = 0; ni < 4; ni++) {
            int m = mt * 16 + arow;
            int nn = n0 + wp * 32 + ni * 8 + bcol * 2;
            if (WHICH != 2) {
                float2 v0 = {acc[mt][ni][0], acc[mt][ni][1]};
                float2 v1 = {acc[mt][ni][2], acc[mt][ni][3]};
                *(float2*)&part[((size_t)kc * 32 + m) * N + nn]     = v0;
                *(float2*)&part[((size_t)kc * 32 + m + 8) * N + nn] = v1;
            } else {
                #pragma unroll
                for (int rr = 0; rr < 2; rr++) {
                    int b = m + rr * 8;
                    size_t base = ((size_t)b * TP1 + t + 1) * Hc;
                    #pragma unroll
                    for (int cc = 0; cc < 2; cc++) {
                        int o = nn + cc;
                        float v = acc[mt][ni][rr * 2 + cc];
                        if (o < Hc) g_U[base + o] = v;
                        else        g_P[base + (o - Hc)] = v;
                    }
                }
            }
        }
    }
}

// -------------------- cell updates -----------------------------------------
__global__ void k_cell0(const float* __restrict__ bih, const float* __restrict__ bhh) {
    int idx = blockIdx.x * 256 + threadIdx.x;
    int b = idx >> 9, h = idx & (Hc - 1);
    float gi = 0, gf = 0, gg = 0, go = 0;
    #pragma unroll
    for (int kc = 0; kc < 11; kc++) {
        const float* p = &g_part0[((size_t)kc * Bc + b) * G4];
        gi += p[h]; gf += p[h + Hc]; gg += p[h + 2 * Hc]; go += p[h + 3 * Hc];
    }
    gi += bih[h] + bhh[h];
    gf += bih[h + Hc] + bhh[h + Hc];
    gg += bih[h + 2 * Hc] + bhh[h + 2 * Hc];
    go += bih[h + 3 * Hc] + bhh[h + 3 * Hc];
    float c = sigf(gf) * g_c0[idx] + sigf(gi) * tanhf(gg);
    g_c0[idx] = c;
    float hn = sigf(go) * tanhf(c);
    g_X0[b * XK0 + 2304 + h] = hn;   // for next step's gates0
    g_X1[b * XK1c + h]       = hn;   // for this step's gates1
}

__global__ void k_cell1(int t, const float* __restrict__ bih, const float* __restrict__ bhh) {
    int idx = blockIdx.x * 256 + threadIdx.x;
    int b = idx >> 9, h = idx & (Hc - 1);
    float gi = 0, gf = 0, gg = 0, go = 0;
    #pragma unroll
    for (int kc = 0; kc < 8; kc++) {
        const float* p = &g_part1[((size_t)kc * Bc + b) * G4];
        gi += p[h]; gf += p[h + Hc]; gg += p[h + 2 * Hc]; go += p[h + 3 * Hc];
    }
    gi += bih[h] + bhh[h];
    gf += bih[h + Hc] + bhh[h + Hc];
    gg += bih[h + 2 * Hc] + bhh[h + 2 * Hc];
    go += bih[h + 3 * Hc] + bhh[h + 3 * Hc];
    float c = sigf(gf) * g_c1[idx] + sigf(gi) * tanhf(gg);
    g_c1[idx] = c;
    float hn = sigf(go) * tanhf(c);
    g_buf[((size_t)b * TP1 + t + 1) * Hc + h] = hn;
    g_cat[((size_t)t * Bc + b) * CATc + h]    = hn;
    g_X1[b * XK1c + Hc + h]                   = hn;   // h1 for next step's gates1
}

// -------------------- batched logits GEMM (bf16 mma, fp32 accum) -----------
__device__ __forceinline__ void mma16816(float* d, const uint32_t* a, const uint32_t* b) {
    asm volatile(
        "mma.sync.aligned.m16n8k16.row.col.f32.bf16.bf16.f32 "
        "{%0,%1,%2,%3}, {%4,%5,%6,%7}, {%8,%9}, {%0,%1,%2,%3};\n"
        : "+f"(d[0]), "+f"(d[1]), "+f"(d[2]), "+f"(d[3])
        : "r"(a[0]), "r"(a[1]), "r"(a[2]), "r"(a[3]), "r"(b[0]), "r"(b[1]));
}

#define SST 48  // smem row stride (elements); 96B rows -> 16B aligned uint4 stores

__global__ void __launch_bounds__(256) k_logits(const float* __restrict__ bo,
                                                float* __restrict__ out) {
    __shared__ __nv_bfloat16 As[2][128 * SST];
    __shared__ __nv_bfloat16 Bs[2][128 * SST];
    // m fast-varying: a wave of 148 CTAs covers all 24 m-tiles x ~6 n-tiles,
    // so Wo (164MB > L2) streams from DRAM ~once.
    int m0 = blockIdx.x * 128, n0 = blockIdx.y * 128;
    int tid = threadIdx.x, lane = tid & 31, wid = tid >> 5;
    int wm = wid >> 2, wn = wid & 3;   // 2x4 warps; warp tile 64m x 32n
    float acc[4][4][4];
    #pragma unroll
    for (int i = 0; i < 4; i++)
        #pragma unroll
        for (int j = 0; j < 4; j++)
            #pragma unroll
            for (int q = 0; q < 4; q++) acc[i][j][q] = 0.f;

    uint4 ra[2], rb[2];
    int gr = lane >> 2, cc = (lane & 3) * 2;
    int mb = wm * 64, nb = wn * 32;

    auto fetch = [&](int ko) {
        #pragma unroll
        for (int i = 0; i < 2; i++) {
            int lin = tid + i * 256;
            int r = lin >> 2, kq = lin & 3;
            ra[i] = *(const uint4*)&g_cat_bf[(size_t)(m0 + r) * CATc + ko + kq * 8];
            rb[i] = *(const uint4*)&g_Wo_bf[(size_t)(n0 + r) * CATc + ko + kq * 8];
        }
    };
    auto stash = [&](int s) {
        #pragma unroll
        for (int i = 0; i < 2; i++) {
            int lin = tid + i * 256;
            int r = lin >> 2, kq = lin & 3;
            *(uint4*)&As[s][r * SST + kq * 8] = ra[i];
            *(uint4*)&Bs[s][r * SST + kq * 8] = rb[i];
        }
    };
    auto compute = [&](int s) {
        #pragma unroll
        for (int ks = 0; ks < 32; ks += 16) {
            uint32_t af[4][4], bfr[4][2];
            #pragma unroll
            for (int mi = 0; mi < 4; mi++) {
                const __nv_bfloat16* base = &As[s][(mb + mi * 16 + gr) * SST + ks + cc];
                af[mi][0] = *(const uint32_t*)base;
                af[mi][1] = *(const uint32_t*)(base + 8 * SST);
                af[mi][2] = *(const uint32_t*)(base + 8);
                af[mi][3] = *(const uint32_t*)(base + 8 * SST + 8);
            }
            #pragma unroll
            for (int ni = 0; ni < 4; ni++) {
                const __nv_bfloat16* bbase = &Bs[s][(nb + ni * 8 + gr) * SST + ks + cc];
                bfr[ni][0] = *(const uint32_t*)bbase;
                bfr[ni][1] = *(const uint32_t*)(bbase + 8);
            }
            #pragma unroll
            for (int mi = 0; mi < 4; mi++)
                #pragma unroll
                for (int ni = 0; ni < 4; ni++)
                    mma16816(acc[mi][ni], af[mi], bfr[ni]);
        }
    };

    fetch(0); stash(0);
    __syncthreads();
    for (int kt = 0; kt < 80; kt++) {
        if (kt < 79) fetch((kt + 1) * 32);
        compute(kt & 1);
        if (kt < 79) stash((kt + 1) & 1);
        __syncthreads();
    }

    // epilogue: + bias, remap m=t*B+b -> row b*T+t
    #pragma unroll
    for (int mi = 0; mi < 4; mi++) {
        #pragma unroll
        for (int ni = 0; ni < 4; ni++) {
            int m = m0 + mb + mi * 16 + gr;
            int n = n0 + nb + ni * 8 + cc;
            float b0 = bo[n], b1 = bo[n + 1];
            int bi = m & 31, tt = m >> 5;
            size_t r0 = ((size_t)bi * Tc + tt) * Vc;
            out[r0 + n]     = acc[mi][ni][0] + b0;
            out[r0 + n + 1] = acc[mi][ni][1] + b1;
            int m2 = m + 8;
            int bi2 = m2 & 31, tt2 = m2 >> 5;
            size_t r1 = ((size_t)bi2 * Tc + tt2) * Vc;
            out[r1 + n]     = acc[mi][ni][2] + b0;
            out[r1 + n + 1] = acc[mi][ni][3] + b1;
        }
    }
}

// -------------------- row-wise log-softmax ---------------------------------
__global__ void k_lsm(float* __restrict__ out) {
    __shared__ float red[8];
    size_t base = (size_t)blockIdx.x * Vc;
    int tid = threadIdx.x, lane = tid & 31, w = tid >> 5;
    float m = -1e30f;
    for (int i = tid; i < Vc; i += 256) m = fmaxf(m, out[base + i]);
    #pragma unroll
    for (int o = 16; o; o >>= 1) m = fmaxf(m, __shfl_xor_sync(0xffffffffu, m, o));
    if (lane == 0) red[w] = m;
    __syncthreads();
    if (tid == 0) {
        float mm = red[0];
        #pragma unroll
        for (int i = 1; i < 8; i++) mm = fmaxf(mm, red[i]);
        red[0] = mm;
    }
    __syncthreads();
    m = red[0];
    __syncthreads();
    float s = 0.f;
    for (int i = tid; i < Vc; i += 256) s += __expf(out[base + i] - m);
    #pragma unroll
    for (int o = 16; o; o >>= 1) s += __shfl_xor_sync(0xffffffffu, s, o);
    if (lane == 0) red[w] = s;
    __syncthreads();
    if (tid == 0) {
        float ss = 0.f;
        #pragma unroll
        for (int i = 1; i < 8; i++) ss += red[i];
        red[0] += ss;
    }
    __syncthreads();
    float lse = m + logf(red[0]);
    for (int i = tid; i < Vc; i += 256) out[base + i] -= lse;
}

// -------------------- launch -----------------------------------------------
extern "C" void kernel_launch(void* const* d_in, const int* in_sizes, int n_in,
                              void* d_out, int out_size) {
    const float* inputs = (const float*)d_in[0];
    const float* W_ih0  = (const float*)d_in[1];
    const float* W_hh0  = (const float*)d_in[2];
    const float* b_ih0  = (const float*)d_in[3];
    const float* b_hh0  = (const float*)d_in[4];
    const float* W_ih1  = (const float*)d_in[5];
    const float* W_hh1  = (const float*)d_in[6];
    const float* b_ih1  = (const float*)d_in[7];
    const float* b_hh1  = (const float*)d_in[8];
    const float* Wa1    = (const float*)d_in[9];
    const float* ba1    = (const float*)d_in[10];
    const float* Wa2    = (const float*)d_in[11];
    const float* ba2    = (const float*)d_in[12];
    const float* Wo     = (const float*)d_in[13];
    const float* bo     = (const float*)d_in[14];
    float* out = (float*)d_out;

    k_init<<<64, 256>>>();
    k_prep_w0<<<1480, 256>>>(W_ih0, W_hh0);
    k_prep_w1<<<512, 256>>>(W_ih1, W_hh1);
    k_prep_wa<<<256, 256>>>(Wa1);
    k_cvt_wo<<<2048, 256>>>(Wo);

    for (int t = 0; t < Tc; t++) {
        k_attn<<<Bc, 256>>>(t, inputs, Wa2, ba1, ba2);
        k_gemm<0><<<dim3(16, 11), 128>>>(t);
        k_cell0<<<64, 256>>>(b_ih0, b_hh0);
        k_gemm<1><<<dim3(16, 8), 128>>>(t);
        k_cell1<<<64, 256>>>(t, b_ih1, b_hh1);
        k_gemm<2><<<dim3(8, 1), 128>>>(t);
    }

    k_cvt_cat<<<7680, 256>>>();
    dim3 gg((Bc * Tc) / 128, Vc / 128);   // (24, 250), m fast
    k_logits<<<gg, 256>>>(bo, out);
    k_lsm<<<Bc * Tc, 256>>>(out);
}